// round 16
// baseline (speedup 1.0000x reference)
#include <cuda_runtime.h>
#include <cstdint>

#define Bb 8
#define Ss 512
#define Ee 64
#define Hh 8

// smem layout (floats), all offsets chosen for bank-conflict freedom
#define HSTRIDE   4100                    // 8*512 + 4 pad  (≡16B mod 128B)
#define QT_FLOATS (Hh * HSTRIDE)          // 32800
#define WT_OFF    QT_FLOATS
#define WT_STRIDE 66                      // even -> 8B-aligned pair loads
#define WT_FLOATS (64 * WT_STRIDE)        // 4224
#define CTX_OFF   (WT_OFF + WT_FLOATS)    // 37024
#define CTX_STRIDE 68                     // ≡16B mod 128B
#define SMEM_FLOATS (CTX_OFF + 32 * CTX_STRIDE)
#define SMEM_BYTES  (SMEM_FLOATS * 4)     // 156,800 B dynamic

// packed fp32x2 helpers (sm_103a FFMA2 path)
#define FMA_X2(d, a, b, c) \
    asm("fma.rn.f32x2 %0, %1, %2, %3;" : "=l"(d) : "l"(a), "l"(b), "l"(c))
#define MUL_X2(d, a, b) \
    asm("mul.rn.f32x2 %0, %1, %2;" : "=l"(d) : "l"(a), "l"(b))
#define ADD_X2(d, a, b) \
    asm("add.rn.f32x2 %0, %1, %2;" : "=l"(d) : "l"(a), "l"(b))

__device__ __forceinline__ uint64_t pack2(float lo, float hi) {
    uint64_t u;
    unsigned a = __float_as_uint(lo), b = __float_as_uint(hi);
    asm("mov.b64 %0, {%1, %2};" : "=l"(u) : "r"(a), "r"(b));
    return u;
}
__device__ __forceinline__ void unpack2(uint64_t u, float& lo, float& hi) {
    unsigned a, b;
    asm("mov.b64 {%0, %1}, %2;" : "=r"(a), "=r"(b) : "l"(u));
    lo = __uint_as_float(a); hi = __uint_as_float(b);
}

// ---------------------------------------------------------------------------
// Mega kernel: analytic quantum heads + self-attention + output projection.
// grid = 8 batches x 16 row-chunks = 128 blocks (single wave), 256 threads.
// Each block:
//   1. builds the full transposed q-tile qT[h][d][s] (512 tokens, 8 heads)
//      for its batch in dynamic smem + loads W_o transposed,
//   2. thread (r, h) = (tid>>3, tid&7) runs attention for query row
//      row0+r, head h over all 512 keys (packed f32x2 over key pairs),
//   3. stages ctx fragments in smem, applies W_o + bias, writes output.
// ---------------------------------------------------------------------------
__global__ __launch_bounds__(256) void mega_kernel(
        const float* __restrict__ x,
        const float* __restrict__ theta,
        const float* __restrict__ Wo,
        const float* __restrict__ bo,
        float* __restrict__ out) {
    extern __shared__ float sm[];
    const int tid  = threadIdx.x;
    const int b    = blockIdx.x >> 4;
    const int row0 = (blockIdx.x & 15) * 32;

    // ---- W_o transposed fill: Wt[e*66 + j] = Wo[j*64 + e] ----
    const float4* Wo4 = reinterpret_cast<const float4*>(Wo);
#pragma unroll
    for (int i = tid; i < 1024; i += 256) {
        float4 w = Wo4[i];
        int j = i >> 4, e0 = (i & 15) * 4;
        sm[WT_OFF + (e0 + 0) * WT_STRIDE + j] = w.x;
        sm[WT_OFF + (e0 + 1) * WT_STRIDE + j] = w.y;
        sm[WT_OFF + (e0 + 2) * WT_STRIDE + j] = w.z;
        sm[WT_OFF + (e0 + 3) * WT_STRIDE + j] = w.w;
    }

    // ---- build transposed q tile for the whole batch ----
    float th[8];
#pragma unroll
    for (int w = 0; w < 8; w++) th[w] = __ldg(theta + w);

#pragma unroll
    for (int u = tid; u < Ss * Hh; u += 256) {   // 16 units per thread
        int s = u >> 3, hu = u & 7;
        const float4* xr = reinterpret_cast<const float4*>(
            x + ((b * Ss + s) * Ee + hu * 8));
        float4 x0 = xr[0];
        float4 x1 = xr[1];
        float a[8] = {x0.x, x0.y, x0.z, x0.w, x1.x, x1.y, x1.z, x1.w};
        float c[8];
#pragma unroll
        for (int w = 0; w < 8; w++) c[w] = __cosf(a[w] + th[w]);
        float z[8];
        float pre = c[0];
#pragma unroll
        for (int w = 1; w < 8; w++) { pre *= c[w]; z[w] = pre; }
        float suf = 1.0f;
#pragma unroll
        for (int w = 7; w >= 1; w--) suf *= c[w];
        z[0] = suf;
        float* qh = sm + hu * HSTRIDE;
#pragma unroll
        for (int d = 0; d < 8; d++) qh[d * Ss + s] = z[d];   // conflict-free
    }
    __syncthreads();

    // ---- attention: thread (r, h), all 512 keys ----
    const int r  = tid >> 3;
    const int h  = tid & 7;
    const int sq = row0 + r;
    const float* qh = sm + h * HSTRIDE;

    const float kscale = 0.35355339059327373f * 1.4426950408889634f;
    uint64_t mP[8];
#pragma unroll
    for (int d = 0; d < 8; d++) {
        float m = qh[d * Ss + sq] * kscale;
        mP[d] = pack2(m, m);
    }

    uint64_t acc[8];
#pragma unroll
    for (int d = 0; d < 8; d++) acc[d] = 0;
    uint64_t lP = 0;

#pragma unroll 2
    for (int t = 0; t < Ss; t += 4) {
        ulonglong2 kd[8];
#pragma unroll
        for (int d = 0; d < 8; d++)
            kd[d] = *reinterpret_cast<const ulonglong2*>(qh + d * Ss + t);

        uint64_t xa, ya;                  // scores (t,t+1) and (t+2,t+3)
        MUL_X2(xa, mP[0], kd[0].x);
        MUL_X2(ya, mP[0], kd[0].y);
#pragma unroll
        for (int d = 1; d < 8; d++) {
            FMA_X2(xa, mP[d], kd[d].x, xa);
            FMA_X2(ya, mP[d], kd[d].y, ya);
        }
        float s0, s1, s2, s3;
        unpack2(xa, s0, s1);
        unpack2(ya, s2, s3);
        float p0, p1, p2, p3;
        asm("ex2.approx.f32 %0, %1;" : "=f"(p0) : "f"(s0));
        asm("ex2.approx.f32 %0, %1;" : "=f"(p1) : "f"(s1));
        asm("ex2.approx.f32 %0, %1;" : "=f"(p2) : "f"(s2));
        asm("ex2.approx.f32 %0, %1;" : "=f"(p3) : "f"(s3));
        uint64_t pA = pack2(p0, p1);
        uint64_t pB = pack2(p2, p3);
        ADD_X2(lP, lP, pA);
        ADD_X2(lP, lP, pB);
#pragma unroll
        for (int d = 0; d < 8; d++) {
            FMA_X2(acc[d], pA, kd[d].x, acc[d]);
            FMA_X2(acc[d], pB, kd[d].y, acc[d]);
        }
    }

    // ---- finalize softmax, stage ctx fragment ----
    float lo, hi;
    unpack2(lP, lo, hi);
    float inv = __frcp_rn(lo + hi);
    float rr[8];
#pragma unroll
    for (int d = 0; d < 8; d++) {
        unpack2(acc[d], lo, hi);
        rr[d] = (lo + hi) * inv;
    }
    float* crow = sm + CTX_OFF + r * CTX_STRIDE + h * 8;
    reinterpret_cast<float4*>(crow)[0] = make_float4(rr[0], rr[1], rr[2], rr[3]);
    reinterpret_cast<float4*>(crow)[1] = make_float4(rr[4], rr[5], rr[6], rr[7]);
    __syncthreads();

    // ---- projection: thread (r, h) -> out[row sq][h*8 .. h*8+8) ----
    const float* ctxr = sm + CTX_OFF + r * CTX_STRIDE;
    const int j0 = h * 8;
    uint64_t pacc[4];
#pragma unroll
    for (int k = 0; k < 4; k++)
        pacc[k] = pack2(__ldg(bo + j0 + 2 * k), __ldg(bo + j0 + 2 * k + 1));
#pragma unroll 4
    for (int e = 0; e < 64; e++) {
        float ce = ctxr[e];
        uint64_t cc = pack2(ce, ce);
        const uint64_t* wrow = reinterpret_cast<const uint64_t*>(
            sm + WT_OFF + e * WT_STRIDE + j0);
#pragma unroll
        for (int k = 0; k < 4; k++) FMA_X2(pacc[k], cc, wrow[k], pacc[k]);
    }
    float o[8];
#pragma unroll
    for (int k = 0; k < 4; k++) unpack2(pacc[k], o[2 * k], o[2 * k + 1]);
    float4* o4 = reinterpret_cast<float4*>(out + (b * Ss + sq) * Ee + j0);
    o4[0] = make_float4(o[0], o[1], o[2], o[3]);
    o4[1] = make_float4(o[4], o[5], o[6], o[7]);
}

// ---------------------------------------------------------------------------
extern "C" void kernel_launch(void* const* d_in, const int* in_sizes, int n_in,
                              void* d_out, int out_size) {
    const float* x     = (const float*)d_in[0];
    const float* theta = (const float*)d_in[1];
    const float* Wo    = (const float*)d_in[2];
    const float* bo    = (const float*)d_in[3];
    float* out = (float*)d_out;
    (void)in_sizes; (void)n_in; (void)out_size;

    cudaFuncSetAttribute(mega_kernel,
                         cudaFuncAttributeMaxDynamicSharedMemorySize,
                         SMEM_BYTES);
    mega_kernel<<<Bb * 16, 256, SMEM_BYTES>>>(x, theta, Wo, bo, out);
}

// round 17
// speedup vs baseline: 1.2424x; 1.2424x over previous
#include <cuda_runtime.h>
#include <cstdint>

#define Bb 8
#define Ss 512
#define Ee 64
#define Hh 8

// smem layout (floats)
#define HSTRIDE   4100                    // 8*512 + 4 pad  (≡16B mod 128B)
#define QT_FLOATS (Hh * HSTRIDE)          // 32800
#define WT_OFF    QT_FLOATS
#define WT_STRIDE 66                      // even -> 8B-aligned pair loads
#define WT_FLOATS (64 * WT_STRIDE)        // 4224
#define CTX_OFF   (WT_OFF + WT_FLOATS)    // 37024
#define CTX_STRIDE 65                     // bank = (r + e) mod 32 -> conflict-free
#define SMEM_FLOATS (CTX_OFF + 32 * CTX_STRIDE)
#define SMEM_BYTES  (SMEM_FLOATS * 4)     // ~156.4 KB dynamic

// packed fp32x2 helpers (sm_103a FFMA2 path)
#define FMA_X2(d, a, b, c) \
    asm("fma.rn.f32x2 %0, %1, %2, %3;" : "=l"(d) : "l"(a), "l"(b), "l"(c))
#define MUL_X2(d, a, b) \
    asm("mul.rn.f32x2 %0, %1, %2;" : "=l"(d) : "l"(a), "l"(b))
#define ADD_X2(d, a, b) \
    asm("add.rn.f32x2 %0, %1, %2;" : "=l"(d) : "l"(a), "l"(b))

__device__ __forceinline__ uint64_t pack2(float lo, float hi) {
    uint64_t u;
    unsigned a = __float_as_uint(lo), b = __float_as_uint(hi);
    asm("mov.b64 %0, {%1, %2};" : "=l"(u) : "r"(a), "r"(b));
    return u;
}
__device__ __forceinline__ void unpack2(uint64_t u, float& lo, float& hi) {
    unsigned a, b;
    asm("mov.b64 {%0, %1}, %2;" : "=r"(a), "=r"(b) : "l"(u));
    lo = __uint_as_float(a); hi = __uint_as_float(b);
}

// ---------------------------------------------------------------------------
// Mega kernel v2: quantum heads + attention + projection, fully fused.
// grid = 8 batches x 16 row-chunks = 128 blocks (single wave), 256 threads.
// CRITICAL LAYOUT: warp = one head (h = tid>>5, r = tid&31) so every key
// LDS.128 in the attention loop is warp-uniform -> broadcast, 1 wavefront.
// ---------------------------------------------------------------------------
__global__ __launch_bounds__(256) void mega_kernel(
        const float* __restrict__ x,
        const float* __restrict__ theta,
        const float* __restrict__ Wo,
        const float* __restrict__ bo,
        float* __restrict__ out) {
    extern __shared__ float sm[];
    const int tid  = threadIdx.x;
    const int b    = blockIdx.x >> 4;
    const int row0 = (blockIdx.x & 15) * 32;

    // ---- W_o transposed fill: Wt[e*66 + j] = Wo[j*64 + e] ----
    const float4* Wo4 = reinterpret_cast<const float4*>(Wo);
#pragma unroll
    for (int i = tid; i < 1024; i += 256) {
        float4 w = Wo4[i];
        int j = i >> 4, e0 = (i & 15) * 4;
        sm[WT_OFF + (e0 + 0) * WT_STRIDE + j] = w.x;
        sm[WT_OFF + (e0 + 1) * WT_STRIDE + j] = w.y;
        sm[WT_OFF + (e0 + 2) * WT_STRIDE + j] = w.z;
        sm[WT_OFF + (e0 + 3) * WT_STRIDE + j] = w.w;
    }

    // ---- build transposed q tile for the whole batch ----
    float th[8];
#pragma unroll
    for (int w = 0; w < 8; w++) th[w] = __ldg(theta + w);

#pragma unroll
    for (int u = tid; u < Ss * Hh; u += 256) {   // 16 units per thread
        int s = u >> 3, hu = u & 7;
        const float4* xr = reinterpret_cast<const float4*>(
            x + ((b * Ss + s) * Ee + hu * 8));
        float4 x0 = xr[0];
        float4 x1 = xr[1];
        float a[8] = {x0.x, x0.y, x0.z, x0.w, x1.x, x1.y, x1.z, x1.w};
        float c[8];
#pragma unroll
        for (int w = 0; w < 8; w++) c[w] = __cosf(a[w] + th[w]);
        float z[8];
        float pre = c[0];
#pragma unroll
        for (int w = 1; w < 8; w++) { pre *= c[w]; z[w] = pre; }
        float suf = 1.0f;
#pragma unroll
        for (int w = 7; w >= 1; w--) suf *= c[w];
        z[0] = suf;
        float* qh = sm + hu * HSTRIDE;
#pragma unroll
        for (int d = 0; d < 8; d++) qh[d * Ss + s] = z[d];   // conflict-free
    }
    __syncthreads();

    // ---- attention: warp = head h, lane = row r; all 512 keys ----
    const int r  = tid & 31;
    const int h  = tid >> 5;
    const int sq = row0 + r;
    const float* qh = sm + h * HSTRIDE;

    const float kscale = 0.35355339059327373f * 1.4426950408889634f;
    uint64_t mP[8];
#pragma unroll
    for (int d = 0; d < 8; d++) {
        float m = qh[d * Ss + sq] * kscale;
        mP[d] = pack2(m, m);
    }

    uint64_t acc[8];
#pragma unroll
    for (int d = 0; d < 8; d++) acc[d] = 0;
    uint64_t lP = 0;

#pragma unroll 2
    for (int t = 0; t < Ss; t += 4) {
        // warp-uniform addresses -> broadcast LDS.128, 1 wavefront each
        ulonglong2 kd[8];
#pragma unroll
        for (int d = 0; d < 8; d++)
            kd[d] = *reinterpret_cast<const ulonglong2*>(qh + d * Ss + t);

        uint64_t xa, ya;                  // scores (t,t+1) and (t+2,t+3)
        MUL_X2(xa, mP[0], kd[0].x);
        MUL_X2(ya, mP[0], kd[0].y);
#pragma unroll
        for (int d = 1; d < 8; d++) {
            FMA_X2(xa, mP[d], kd[d].x, xa);
            FMA_X2(ya, mP[d], kd[d].y, ya);
        }
        float s0, s1, s2, s3;
        unpack2(xa, s0, s1);
        unpack2(ya, s2, s3);
        float p0, p1, p2, p3;
        asm("ex2.approx.f32 %0, %1;" : "=f"(p0) : "f"(s0));
        asm("ex2.approx.f32 %0, %1;" : "=f"(p1) : "f"(s1));
        asm("ex2.approx.f32 %0, %1;" : "=f"(p2) : "f"(s2));
        asm("ex2.approx.f32 %0, %1;" : "=f"(p3) : "f"(s3));
        uint64_t pA = pack2(p0, p1);
        uint64_t pB = pack2(p2, p3);
        ADD_X2(lP, lP, pA);
        ADD_X2(lP, lP, pB);
#pragma unroll
        for (int d = 0; d < 8; d++) {
            FMA_X2(acc[d], pA, kd[d].x, acc[d]);
            FMA_X2(acc[d], pB, kd[d].y, acc[d]);
        }
    }

    // ---- finalize softmax, stage ctx fragment (scalar, conflict-free) ----
    float lo, hi;
    unpack2(lP, lo, hi);
    float inv = __frcp_rn(lo + hi);
    float* crow = sm + CTX_OFF + r * CTX_STRIDE + h * 8;
#pragma unroll
    for (int d = 0; d < 8; d++) {
        unpack2(acc[d], lo, hi);
        crow[d] = (lo + hi) * inv;     // bank = (r + h*8 + d) mod 32, distinct
    }
    __syncthreads();

    // ---- projection: thread (r, h) -> out[row sq][h*8 .. h*8+8) ----
    const float* ctxr = sm + CTX_OFF + r * CTX_STRIDE;
    const int j0 = h * 8;
    uint64_t pacc[4];
#pragma unroll
    for (int k = 0; k < 4; k++)
        pacc[k] = pack2(__ldg(bo + j0 + 2 * k), __ldg(bo + j0 + 2 * k + 1));
#pragma unroll 4
    for (int e = 0; e < 64; e++) {
        float ce = ctxr[e];            // bank = (r + e) mod 32, conflict-free
        uint64_t cc = pack2(ce, ce);
        const uint64_t* wrow = reinterpret_cast<const uint64_t*>(
            sm + WT_OFF + e * WT_STRIDE + j0);   // warp-uniform -> broadcast
#pragma unroll
        for (int k = 0; k < 4; k++) FMA_X2(pacc[k], cc, wrow[k], pacc[k]);
    }
    float o[8];
#pragma unroll
    for (int k = 0; k < 4; k++) unpack2(pacc[k], o[2 * k], o[2 * k + 1]);
    float4* o4 = reinterpret_cast<float4*>(out + (b * Ss + sq) * Ee + j0);
    o4[0] = make_float4(o[0], o[1], o[2], o[3]);
    o4[1] = make_float4(o[4], o[5], o[6], o[7]);
}

// ---------------------------------------------------------------------------
extern "C" void kernel_launch(void* const* d_in, const int* in_sizes, int n_in,
                              void* d_out, int out_size) {
    const float* x     = (const float*)d_in[0];
    const float* theta = (const float*)d_in[1];
    const float* Wo    = (const float*)d_in[2];
    const float* bo    = (const float*)d_in[3];
    float* out = (float*)d_out;
    (void)in_sizes; (void)n_in; (void)out_size;

    cudaFuncSetAttribute(mega_kernel,
                         cudaFuncAttributeMaxDynamicSharedMemorySize,
                         SMEM_BYTES);
    mega_kernel<<<Bb * 16, 256, SMEM_BYTES>>>(x, theta, Wo, bo, out);
}